// round 16
// baseline (speedup 1.0000x reference)
#include <cuda_runtime.h>
#include <cuda_bf16.h>
#include <cstdint>

// YOLO loss: N=64, S=128, B=2.
// input (N,S,S,10) fp32, target (N,S,S,5) fp32 -> 5 fp32 scalars.
// 592 CTAs (148 SMs x 4) x 256 threads; 4096 tiles of 256 cells claimed via
// a global ticket counter (perfect SM load balance), streamed through R9's
// double-buffered cp.async pipeline.

#define NCELLS (64 * 128 * 128)
#define THREADS 256
#define NWARPS (THREADS / 32)
#define TILE 256
#define TOTAL_TILES (NCELLS / TILE)   // 4096
#define GRID 592                      // 148 x 4, exactly 4 CTAs per SM

#define IN_F4_PER_TILE (TILE * 10 / 4)   // 640 float4
#define TG_F4_PER_TILE (TILE * 5 / 4)    // 320 float4

__device__ float g_acc[6];   // 0:S_noobj 1:S_xy 2:S_wh 3:S_obj 4:S_nresp 5:m
__device__ unsigned int g_count;
__device__ unsigned int g_ticket;

__device__ __forceinline__ float softplus_fast(float x) {
    return fmaxf(x, 0.0f) + __logf(1.0f + __expf(-fabsf(x)));
}
__device__ __forceinline__ float sigmoid_fast(float x) {
    return __fdividef(1.0f, 1.0f + __expf(-x));
}
__device__ __forceinline__ void cp_async16(unsigned int smem_addr, const void* gptr) {
    asm volatile("cp.async.cg.shared.global [%0], [%1], 16;"
                 :: "r"(smem_addr), "l"(gptr) : "memory");
}

// Branchless single-cell processing.
__device__ __forceinline__ void process_cell(
    float l0, float x0, float y0, float w0, float h0,
    float l1, float x1, float y1, float w1, float h1,
    float tconf, float tx, float ty, float tw, float th,
    float& s_noobj, float& s_xy, float& s_wh,
    float& s_obj, float& s_nresp, float& s_m)
{
    float obj = (tconf > 0.0f) ? 1.0f : 0.0f;
    float noobj = 1.0f - obj;

    float bce0_0 = softplus_fast(l0);
    float bce0_1 = softplus_fast(l1);

    s_noobj += noobj * (bce0_0 + bce0_1);
    s_m += obj;

    float c0x = sigmoid_fast(x0), c0y = sigmoid_fast(y0);
    float c0w = sigmoid_fast(w0), c0h = sigmoid_fast(h0);
    float c1x = sigmoid_fast(x1), c1y = sigmoid_fast(y1);
    float c1w = sigmoid_fast(w1), c1h = sigmoid_fast(h1);

    float tlx = tx - tw * 0.5f, tly = ty - th * 0.5f;
    float trx = tx + tw * 0.5f, trY = ty + th * 0.5f;
    float area_t = tw * th;

    float wx0 = fmaxf(0.0f, fminf(c0x + c0w * 0.5f, trx) - fmaxf(c0x - c0w * 0.5f, tlx));
    float wy0 = fmaxf(0.0f, fminf(c0y + c0h * 0.5f, trY) - fmaxf(c0y - c0h * 0.5f, tly));
    float inter0 = wx0 * wy0;
    float den0 = c0w * c0h + area_t - inter0 + 1e-10f;

    float wx1 = fmaxf(0.0f, fminf(c1x + c1w * 0.5f, trx) - fmaxf(c1x - c1w * 0.5f, tlx));
    float wy1 = fmaxf(0.0f, fminf(c1y + c1h * 0.5f, trY) - fmaxf(c1y - c1h * 0.5f, tly));
    float inter1 = wx1 * wy1;
    float den1 = c1w * c1h + area_t - inter1 + 1e-10f;

    // argmax(iou): box1 wins iff strictly greater (first-max tie-break);
    // denominators > 0 -> cross-product compare, no division.
    bool r1 = inter1 * den0 > inter0 * den1;

    float rx = r1 ? c1x : c0x, ry = r1 ? c1y : c0y;
    float rw = r1 ? c1w : c0w, rh = r1 ? c1h : c0h;
    float rl = r1 ? l1 : l0;
    float rb = r1 ? bce0_1 : bce0_0;
    float nb = r1 ? bce0_0 : bce0_1;

    float dx = rx - tx, dy = ry - ty, dw = rw - tw, dh = rh - th;
    s_xy    += obj * (dx * dx + dy * dy);
    s_wh    += obj * (dw * dw + dh * dh);
    s_obj   += obj * (rb - rl);
    s_nresp += obj * nb;
}

__shared__ union __align__(16) SmemU {
    struct {
        float in[2][TILE * 10];   // 2 x 10 KB
        float tg[2][TILE * 5];    // 2 x 5 KB
    } pipe;                       // 30 KB
    float red[6][THREADS];        // 6 KB (reused after pipeline drains)
} sm;
__shared__ int s_tile[2];

__global__ void __launch_bounds__(THREADS)
yolo_fused_kernel(const float* __restrict__ inp, const float* __restrict__ tgt,
                  float* __restrict__ out) {
    int tid = threadIdx.x;

    unsigned int in_addr[2], tg_addr[2];
#pragma unroll
    for (int s = 0; s < 2; s++) {
        in_addr[s] = (unsigned int)__cvta_generic_to_shared(sm.pipe.in[s]);
        tg_addr[s] = (unsigned int)__cvta_generic_to_shared(sm.pipe.tg[s]);
    }

    // prefetch one tile into a stage (coalesced 16B cp.async + commit)
    auto prefetch = [&](int tile, int stage) {
        const float* gi = inp + (size_t)tile * TILE * 10;
        const float* gt = tgt + (size_t)tile * TILE * 5;
#pragma unroll
        for (int i = 0; i < 2; i++) {                      // 512 of 640 float4
            int idx = tid + i * THREADS;
            cp_async16(in_addr[stage] + idx * 16, gi + idx * 4);
        }
        {
            int idx = tid + 2 * THREADS;                   // remaining 128
            if (idx < IN_F4_PER_TILE)
                cp_async16(in_addr[stage] + idx * 16, gi + idx * 4);
        }
        {
            int idx = tid;                                 // 256 of 320 float4
            cp_async16(tg_addr[stage] + idx * 16, gt + idx * 4);
            idx = tid + THREADS;                           // remaining 64
            if (idx < TG_F4_PER_TILE)
                cp_async16(tg_addr[stage] + idx * 16, gt + idx * 4);
        }
        asm volatile("cp.async.commit_group;" ::: "memory");
    };

    float s_noobj = 0.0f, s_xy = 0.0f, s_wh = 0.0f;
    float s_obj = 0.0f, s_nresp = 0.0f, s_m = 0.0f;

    // ---- prologue: claim first ticket, prefetch into stage 0 ----
    if (tid == 0) s_tile[0] = (int)atomicAdd(&g_ticket, 1u);
    __syncthreads();
    int cur = s_tile[0];
    if (cur < TOTAL_TILES) prefetch(cur, 0);

    int stage = 0;
    while (cur < TOTAL_TILES) {
        // claim next ticket; broadcast via smem
        if (tid == 0) s_tile[stage ^ 1] = (int)atomicAdd(&g_ticket, 1u);
        __syncthreads();                      // broadcast + prior stage reads done
        int nxt = s_tile[stage ^ 1];
        bool have_next = (nxt < TOTAL_TILES);
        if (have_next) prefetch(nxt, stage ^ 1);

        // wait for current tile's group (keep next in flight if issued)
        if (have_next)
            asm volatile("cp.async.wait_group 1;" ::: "memory");
        else
            asm volatile("cp.async.wait_group 0;" ::: "memory");
        __syncthreads();                      // tile data visible to all threads

        // process 1 cell per thread from smem
        const float2* ip = reinterpret_cast<const float2*>(sm.pipe.in[stage] + tid * 10);
        float2 a0 = ip[0], a1 = ip[1], a2 = ip[2], a3 = ip[3], a4 = ip[4];
        const float* tp = sm.pipe.tg[stage] + tid * 5;
        float tconf = tp[0], tx = tp[1], ty = tp[2], tw = tp[3], th = tp[4];

        process_cell(a0.x, a0.y, a1.x, a1.y, a2.x,
                     a2.y, a3.x, a3.y, a4.x, a4.y,
                     tconf, tx, ty, tw, th,
                     s_noobj, s_xy, s_wh, s_obj, s_nresp, s_m);

        cur = nxt;
        stage ^= 1;
    }

    // ---- block reduction via smem transpose (reuse pipeline smem) ----
    __syncthreads();
    sm.red[0][tid] = s_noobj;
    sm.red[1][tid] = s_xy;
    sm.red[2][tid] = s_wh;
    sm.red[3][tid] = s_obj;
    sm.red[4][tid] = s_nresp;
    sm.red[5][tid] = s_m;
    __syncthreads();

    int lane = tid & 31;
    int warp = tid >> 5;
    if (warp < 6) {
        float v = 0.0f;
#pragma unroll
        for (int j = 0; j < THREADS / 32; j++)
            v += sm.red[warp][lane + j * 32];
#pragma unroll
        for (int off = 16; off > 0; off >>= 1)
            v += __shfl_xor_sync(0xffffffffu, v, off);
        if (lane == 0)
            atomicAdd(&g_acc[warp], v);
    }
    __syncthreads();

    // ---- last block finalizes + resets for the next graph replay ----
    if (tid == 0) {
        __threadfence();
        unsigned int old = atomicAdd(&g_count, 1u);
        if (old == (unsigned int)(GRID - 1)) {
            volatile float* ga = g_acc;
            float a_noobj = ga[0], a_xy = ga[1], a_wh = ga[2];
            float a_obj = ga[3], a_nresp = ga[4], m = ga[5];
            float n_noobj = (float)NCELLS - m;
            float loss_noobj = a_noobj / (n_noobj * 2.0f) + a_nresp / m;  // B=2
            float loss_xy = a_xy / (m * 2.0f);
            float loss_wh = a_wh / (m * 2.0f);
            float loss_obj = a_obj / m;
            out[0] = loss_noobj + loss_xy + loss_wh + loss_obj;
            out[1] = loss_noobj;
            out[2] = loss_xy;
            out[3] = loss_wh;
            out[4] = loss_obj;
#pragma unroll
            for (int k = 0; k < 6; k++) g_acc[k] = 0.0f;
            g_count = 0u;
            g_ticket = 0u;   // reset ticket for next graph replay
        }
    }
}

extern "C" void kernel_launch(void* const* d_in, const int* in_sizes, int n_in,
                              void* d_out, int out_size) {
    const float* inp = (const float*)d_in[0];
    const float* tgt = (const float*)d_in[1];
    float* out = (float*)d_out;
    yolo_fused_kernel<<<GRID, THREADS>>>(inp, tgt, out);
}

// round 17
// speedup vs baseline: 1.2521x; 1.2521x over previous
#include <cuda_runtime.h>
#include <cuda_bf16.h>
#include <cstdint>

// YOLO loss: N=64, S=128, B=2.
// input (N,S,S,10) fp32, target (N,S,S,5) fp32 -> 5 fp32 scalars.
// R9's double-buffered cp.async pipeline, but GRID=592 (148 SMs x 4) with a
// STATIC balanced split: first 544 CTAs process 7 contiguous tiles, last 48
// process 6. Per-SM load becomes 27-28 tiles (vs 24/32 at GRID=512).

#define NCELLS (64 * 128 * 128)
#define THREADS 256
#define NWARPS (THREADS / 32)
#define TILE 256
#define TOTAL_TILES (NCELLS / TILE)   // 4096
#define GRID 592                      // 148 x 4
#define BIG_CTAS 544                  // 544*7 + 48*6 = 4096

#define IN_F4_PER_TILE (TILE * 10 / 4)   // 640 float4
#define TG_F4_PER_TILE (TILE * 5 / 4)    // 320 float4

__device__ float g_acc[6];   // 0:S_noobj 1:S_xy 2:S_wh 3:S_obj 4:S_nresp 5:m
__device__ unsigned int g_count;

__device__ __forceinline__ float softplus_fast(float x) {
    return fmaxf(x, 0.0f) + __logf(1.0f + __expf(-fabsf(x)));
}
__device__ __forceinline__ float sigmoid_fast(float x) {
    return __fdividef(1.0f, 1.0f + __expf(-x));
}
__device__ __forceinline__ void cp_async16(unsigned int smem_addr, const void* gptr) {
    asm volatile("cp.async.cg.shared.global [%0], [%1], 16;"
                 :: "r"(smem_addr), "l"(gptr) : "memory");
}

// Branchless single-cell processing.
__device__ __forceinline__ void process_cell(
    float l0, float x0, float y0, float w0, float h0,
    float l1, float x1, float y1, float w1, float h1,
    float tconf, float tx, float ty, float tw, float th,
    float& s_noobj, float& s_xy, float& s_wh,
    float& s_obj, float& s_nresp, float& s_m)
{
    float obj = (tconf > 0.0f) ? 1.0f : 0.0f;
    float noobj = 1.0f - obj;

    float bce0_0 = softplus_fast(l0);
    float bce0_1 = softplus_fast(l1);

    s_noobj += noobj * (bce0_0 + bce0_1);
    s_m += obj;

    float c0x = sigmoid_fast(x0), c0y = sigmoid_fast(y0);
    float c0w = sigmoid_fast(w0), c0h = sigmoid_fast(h0);
    float c1x = sigmoid_fast(x1), c1y = sigmoid_fast(y1);
    float c1w = sigmoid_fast(w1), c1h = sigmoid_fast(h1);

    float tlx = tx - tw * 0.5f, tly = ty - th * 0.5f;
    float trx = tx + tw * 0.5f, trY = ty + th * 0.5f;
    float area_t = tw * th;

    float wx0 = fmaxf(0.0f, fminf(c0x + c0w * 0.5f, trx) - fmaxf(c0x - c0w * 0.5f, tlx));
    float wy0 = fmaxf(0.0f, fminf(c0y + c0h * 0.5f, trY) - fmaxf(c0y - c0h * 0.5f, tly));
    float inter0 = wx0 * wy0;
    float den0 = c0w * c0h + area_t - inter0 + 1e-10f;

    float wx1 = fmaxf(0.0f, fminf(c1x + c1w * 0.5f, trx) - fmaxf(c1x - c1w * 0.5f, tlx));
    float wy1 = fmaxf(0.0f, fminf(c1y + c1h * 0.5f, trY) - fmaxf(c1y - c1h * 0.5f, tly));
    float inter1 = wx1 * wy1;
    float den1 = c1w * c1h + area_t - inter1 + 1e-10f;

    // argmax(iou): box1 wins iff strictly greater (first-max tie-break);
    // denominators > 0 -> cross-product compare, no division.
    bool r1 = inter1 * den0 > inter0 * den1;

    float rx = r1 ? c1x : c0x, ry = r1 ? c1y : c0y;
    float rw = r1 ? c1w : c0w, rh = r1 ? c1h : c0h;
    float rl = r1 ? l1 : l0;
    float rb = r1 ? bce0_1 : bce0_0;
    float nb = r1 ? bce0_0 : bce0_1;

    float dx = rx - tx, dy = ry - ty, dw = rw - tw, dh = rh - th;
    s_xy    += obj * (dx * dx + dy * dy);
    s_wh    += obj * (dw * dw + dh * dh);
    s_obj   += obj * (rb - rl);
    s_nresp += obj * nb;
}

__shared__ union __align__(16) SmemU {
    struct {
        float in[2][TILE * 10];   // 2 x 10 KB
        float tg[2][TILE * 5];    // 2 x 5 KB
    } pipe;                       // 30 KB
    float red[6][THREADS];        // 6 KB (reused after pipeline drains)
} sm;

__global__ void __launch_bounds__(THREADS)
yolo_fused_kernel(const float* __restrict__ inp, const float* __restrict__ tgt,
                  float* __restrict__ out) {
    int tid = threadIdx.x;
    int bid = blockIdx.x;

    // static balanced split: CTAs [0,544) -> 7 tiles, [544,592) -> 6 tiles
    int cnt   = (bid < BIG_CTAS) ? 7 : 6;
    int start = (bid < BIG_CTAS) ? bid * 7 : BIG_CTAS * 7 + (bid - BIG_CTAS) * 6;

    const float* gin = inp + (size_t)start * TILE * 10;
    const float* gtg = tgt + (size_t)start * TILE * 5;

    unsigned int in_addr[2], tg_addr[2];
#pragma unroll
    for (int s = 0; s < 2; s++) {
        in_addr[s] = (unsigned int)__cvta_generic_to_shared(sm.pipe.in[s]);
        tg_addr[s] = (unsigned int)__cvta_generic_to_shared(sm.pipe.tg[s]);
    }

    auto prefetch = [&](int t, int stage) {
        const float* gi = gin + (size_t)t * TILE * 10;
        const float* gt = gtg + (size_t)t * TILE * 5;
#pragma unroll
        for (int i = 0; i < 2; i++) {                      // 512 of 640 float4
            int idx = tid + i * THREADS;
            cp_async16(in_addr[stage] + idx * 16, gi + idx * 4);
        }
        {
            int idx = tid + 2 * THREADS;                   // remaining 128
            if (idx < IN_F4_PER_TILE)
                cp_async16(in_addr[stage] + idx * 16, gi + idx * 4);
        }
        {
            int idx = tid;                                 // 256 of 320 float4
            cp_async16(tg_addr[stage] + idx * 16, gt + idx * 4);
            idx = tid + THREADS;                           // remaining 64
            if (idx < TG_F4_PER_TILE)
                cp_async16(tg_addr[stage] + idx * 16, gt + idx * 4);
        }
        asm volatile("cp.async.commit_group;" ::: "memory");
    };

    float s_noobj = 0.0f, s_xy = 0.0f, s_wh = 0.0f;
    float s_obj = 0.0f, s_nresp = 0.0f, s_m = 0.0f;

    prefetch(0, 0);

    for (int t = 0; t < cnt; t++) {
        int stage = t & 1;
        bool have_next = (t + 1 < cnt);
        if (have_next)
            prefetch(t + 1, (t + 1) & 1);

        if (have_next)
            asm volatile("cp.async.wait_group 1;" ::: "memory");
        else
            asm volatile("cp.async.wait_group 0;" ::: "memory");
        __syncthreads();

        // process 1 cell per thread from smem
        const float2* ip = reinterpret_cast<const float2*>(sm.pipe.in[stage] + tid * 10);
        float2 a0 = ip[0], a1 = ip[1], a2 = ip[2], a3 = ip[3], a4 = ip[4];
        const float* tp = sm.pipe.tg[stage] + tid * 5;
        float tconf = tp[0], tx = tp[1], ty = tp[2], tw = tp[3], th = tp[4];

        process_cell(a0.x, a0.y, a1.x, a1.y, a2.x,
                     a2.y, a3.x, a3.y, a4.x, a4.y,
                     tconf, tx, ty, tw, th,
                     s_noobj, s_xy, s_wh, s_obj, s_nresp, s_m);

        __syncthreads();   // all reads done before buffer is overwritten
    }

    // ---- block reduction via smem transpose (reuse pipeline smem) ----
    sm.red[0][tid] = s_noobj;
    sm.red[1][tid] = s_xy;
    sm.red[2][tid] = s_wh;
    sm.red[3][tid] = s_obj;
    sm.red[4][tid] = s_nresp;
    sm.red[5][tid] = s_m;
    __syncthreads();

    int lane = tid & 31;
    int warp = tid >> 5;
    if (warp < 6) {
        float v = 0.0f;
#pragma unroll
        for (int j = 0; j < THREADS / 32; j++)
            v += sm.red[warp][lane + j * 32];
#pragma unroll
        for (int off = 16; off > 0; off >>= 1)
            v += __shfl_xor_sync(0xffffffffu, v, off);
        if (lane == 0)
            atomicAdd(&g_acc[warp], v);
    }
    __syncthreads();

    // ---- last block finalizes + resets for the next graph replay ----
    if (tid == 0) {
        __threadfence();
        unsigned int old = atomicAdd(&g_count, 1u);
        if (old == (unsigned int)(GRID - 1)) {
            volatile float* ga = g_acc;
            float a_noobj = ga[0], a_xy = ga[1], a_wh = ga[2];
            float a_obj = ga[3], a_nresp = ga[4], m = ga[5];
            float n_noobj = (float)NCELLS - m;
            float loss_noobj = a_noobj / (n_noobj * 2.0f) + a_nresp / m;  // B=2
            float loss_xy = a_xy / (m * 2.0f);
            float loss_wh = a_wh / (m * 2.0f);
            float loss_obj = a_obj / m;
            out[0] = loss_noobj + loss_xy + loss_wh + loss_obj;
            out[1] = loss_noobj;
            out[2] = loss_xy;
            out[3] = loss_wh;
            out[4] = loss_obj;
#pragma unroll
            for (int k = 0; k < 6; k++) g_acc[k] = 0.0f;
            g_count = 0u;
        }
    }
}

extern "C" void kernel_launch(void* const* d_in, const int* in_sizes, int n_in,
                              void* d_out, int out_size) {
    const float* inp = (const float*)d_in[0];
    const float* tgt = (const float*)d_in[1];
    float* out = (float*)d_out;
    yolo_fused_kernel<<<GRID, THREADS>>>(inp, tgt, out);
}